// round 16
// baseline (speedup 1.0000x reference)
#include <cuda_runtime.h>
#include <cuda_bf16.h>
#include <cuda_fp16.h>
#include <math.h>
#include <stdint.h>

#define NHEADS 16
#define BSZ    2
#define SEQ    2048
#define CDIM   256
#define HID    1024
#define HD     64
#define ROWS   (BSZ * SEQ)   // 4096
#define QKVW   (3 * HID)     // 3072

// Scratch (allocation-free rule: __device__ globals)
__device__ __half   g_ah[(size_t)ROWS * CDIM];        // 2 MB: array fp16
__device__ __half   g_wh[(size_t)CDIM * QKVW];        // 1.5 MB: Wqkv fp16
__device__ uint32_t g_qk[(size_t)ROWS * 1024];        // 16 MB: q|k bf16x2
__device__ uint32_t g_vh[(size_t)ROWS * 512];         //  8 MB: v fp16x2
__device__ uint32_t g_parth[(size_t)NHEADS * ROWS * 32]; // 8 MB: per-head partials fp16x2

// ---------------------------------------------------------------------------
// helpers
// ---------------------------------------------------------------------------
__device__ __forceinline__ uint32_t pack_bf16x2(float lo, float hi) {
    __nv_bfloat162 h = __floats2bfloat162_rn(lo, hi);
    return *(uint32_t*)&h;
}

__device__ __forceinline__ uint32_t pack_f16x2(float lo, float hi) {
    __half2 h = __floats2half2_rn(lo, hi);
    return *(uint32_t*)&h;
}

__device__ __forceinline__ uint32_t ex2_h2(uint32_t x) {
    uint32_t r;
    asm("ex2.approx.f16x2 %0, %1;\n" : "=r"(r) : "r"(x));
    return r;
}

__device__ __forceinline__ void mma_bf16(
    float* d, uint32_t a0, uint32_t a1, uint32_t a2, uint32_t a3,
    uint32_t b0, uint32_t b1)
{
    asm volatile(
        "mma.sync.aligned.m16n8k16.row.col.f32.bf16.bf16.f32 "
        "{%0,%1,%2,%3}, {%4,%5,%6,%7}, {%8,%9}, {%0,%1,%2,%3};\n"
        : "+f"(d[0]), "+f"(d[1]), "+f"(d[2]), "+f"(d[3])
        : "r"(a0), "r"(a1), "r"(a2), "r"(a3), "r"(b0), "r"(b1));
}

__device__ __forceinline__ void mma_f16(
    float* d, uint32_t a0, uint32_t a1, uint32_t a2, uint32_t a3,
    uint32_t b0, uint32_t b1)
{
    asm volatile(
        "mma.sync.aligned.m16n8k16.row.col.f32.f16.f16.f32 "
        "{%0,%1,%2,%3}, {%4,%5,%6,%7}, {%8,%9}, {%0,%1,%2,%3};\n"
        : "+f"(d[0]), "+f"(d[1]), "+f"(d[2]), "+f"(d[3])
        : "r"(a0), "r"(a1), "r"(a2), "r"(a3), "r"(b0), "r"(b1));
}

__device__ __forceinline__ void ldmatrix_x4(
    uint32_t& r0, uint32_t& r1, uint32_t& r2, uint32_t& r3, uint32_t addr)
{
    asm volatile(
        "ldmatrix.sync.aligned.m8n8.x4.shared.b16 {%0,%1,%2,%3}, [%4];\n"
        : "=r"(r0), "=r"(r1), "=r"(r2), "=r"(r3) : "r"(addr));
}

__device__ __forceinline__ void ldmatrix_x4_trans(
    uint32_t& r0, uint32_t& r1, uint32_t& r2, uint32_t& r3, uint32_t addr)
{
    asm volatile(
        "ldmatrix.sync.aligned.m8n8.x4.trans.shared.b16 {%0,%1,%2,%3}, [%4];\n"
        : "=r"(r0), "=r"(r1), "=r"(r2), "=r"(r3) : "r"(addr));
}

__device__ __forceinline__ void ldmatrix_x2_trans(
    uint32_t& r0, uint32_t& r1, uint32_t addr)
{
    asm volatile(
        "ldmatrix.sync.aligned.m8n8.x2.trans.shared.b16 {%0,%1}, [%2];\n"
        : "=r"(r0), "=r"(r1) : "r"(addr));
}

__device__ __forceinline__ void cp_async16(uint32_t smem_addr, const void* gptr) {
    asm volatile("cp.async.cg.shared.global [%0], [%1], 16;\n"
                 :: "r"(smem_addr), "l"(gptr));
}
__device__ __forceinline__ void cp_commit() {
    asm volatile("cp.async.commit_group;\n");
}

// ---------------------------------------------------------------------------
// fp32 -> fp16 pre-convert
// ---------------------------------------------------------------------------
__global__ __launch_bounds__(256) void f32to16_kernel(
    const float* __restrict__ src, uint32_t* __restrict__ dst)
{
    int i = (blockIdx.x * 256 + threadIdx.x) * 4;
    float4 v = *(const float4*)&src[i];
    uint2 o = make_uint2(pack_f16x2(v.x, v.y), pack_f16x2(v.z, v.w));
    *(uint2*)&dst[i >> 1] = o;
}

// ---------------------------------------------------------------------------
// GEMM1: qkv = array @ Wqkv, pure fp16 mma (proven R12). Epilogue:
// q -> bf16 (x 0.125*log2e), k -> bf16, v -> fp16.
// ---------------------------------------------------------------------------
#define QSCALE 0.180336880f   // 0.125 * log2(e)
#define G1AS 40
#define G1BS 136
#define G1A_H (128 * G1AS)
#define G1B_H (32 * G1BS)
#define G1STAGE_H (G1A_H + G1B_H)
#define G1_SMEM_B (2 * G1STAGE_H * 2)   // 37888 bytes

__global__ __launch_bounds__(256, 2) void gemm_qkv_f16(
    const __half* __restrict__ A, const __half* __restrict__ W,
    uint32_t* __restrict__ QK, uint32_t* __restrict__ VH)
{
    extern __shared__ __half hsm[];

    const int tid = threadIdx.x;
    const int w   = tid >> 5;
    const int wr  = w >> 2;
    const int wc  = w & 3;
    const int l   = tid & 31;
    const int lr  = l >> 2;
    const int lc  = l & 3;
    const int row0 = blockIdx.y * 128;
    const int col0 = blockIdx.x * 128;

    const uint32_t sb = (uint32_t)__cvta_generic_to_shared(hsm);

    auto prefetch = [&](int kt, int s) {
        const int k0 = kt * 32;
        const uint32_t abase = sb + (s * G1STAGE_H) * 2;
        const uint32_t bbase = abase + G1A_H * 2;
        #pragma unroll
        for (int i = 0; i < 2; ++i) {
            int idx = i * 256 + tid;
            int r   = idx >> 2;
            int c8  = (idx & 3) << 3;
            cp_async16(abase + (r * G1AS + c8) * 2,
                       &A[(size_t)(row0 + r) * CDIM + k0 + c8]);
        }
        #pragma unroll
        for (int i = 0; i < 2; ++i) {
            int idx = i * 256 + tid;
            int r   = idx >> 4;
            int c8  = (idx & 15) << 3;
            cp_async16(bbase + (r * G1BS + c8) * 2,
                       &W[(size_t)(k0 + r) * QKVW + col0 + c8]);
        }
        cp_commit();
    };

    float acc[4][4][4] = {};

    prefetch(0, 0);

    const int NKT = CDIM / 32;   // 8
    for (int kt = 0; kt < NKT; ++kt) {
        if (kt + 1 < NKT) {
            prefetch(kt + 1, (kt + 1) & 1);
            asm volatile("cp.async.wait_group 1;\n");
        } else {
            asm volatile("cp.async.wait_group 0;\n");
        }
        __syncthreads();

        const uint32_t sa = sb + ((kt & 1) * G1STAGE_H) * 2;
        const uint32_t sB = sa + G1A_H * 2;

        #pragma unroll
        for (int ks = 0; ks < 2; ++ks) {
            uint32_t af[4][4];
            #pragma unroll
            for (int mi = 0; mi < 4; ++mi) {
                uint32_t addr = sa +
                    ((wr * 64 + mi * 16 + (l & 15)) * G1AS + ks * 16 + (l >> 4) * 8) * 2;
                ldmatrix_x4(af[mi][0], af[mi][1], af[mi][2], af[mi][3], addr);
            }
            uint32_t bf[2][4];
            #pragma unroll
            for (int g = 0; g < 2; ++g) {
                uint32_t addr = sB +
                    ((ks * 16 + (l & 15)) * G1BS + wc * 32 + g * 16 + (l >> 4) * 8) * 2;
                ldmatrix_x4_trans(bf[g][0], bf[g][1], bf[g][2], bf[g][3], addr);
            }
            #pragma unroll
            for (int mi = 0; mi < 4; ++mi)
                #pragma unroll
                for (int g = 0; g < 2; ++g) {
                    mma_f16(acc[mi][2 * g],     af[mi][0], af[mi][1], af[mi][2], af[mi][3],
                            bf[g][0], bf[g][1]);
                    mma_f16(acc[mi][2 * g + 1], af[mi][0], af[mi][1], af[mi][2], af[mi][3],
                            bf[g][2], bf[g][3]);
                }
        }
        __syncthreads();
    }

    #pragma unroll
    for (int mi = 0; mi < 4; ++mi) {
        int gr0 = row0 + wr * 64 + mi * 16 + lr;
        #pragma unroll
        for (int nt = 0; nt < 4; ++nt) {
            int gc = col0 + wc * 32 + nt * 8 + 2 * lc;
            if (gc < HID) {
                QK[(size_t)gr0 * 1024 + (gc >> 1)] =
                    pack_bf16x2(acc[mi][nt][0] * QSCALE, acc[mi][nt][1] * QSCALE);
                QK[(size_t)(gr0 + 8) * 1024 + (gc >> 1)] =
                    pack_bf16x2(acc[mi][nt][2] * QSCALE, acc[mi][nt][3] * QSCALE);
            } else if (gc < 2 * HID) {
                int wi = 512 + ((gc - HID) >> 1);
                QK[(size_t)gr0 * 1024 + wi] =
                    pack_bf16x2(acc[mi][nt][0], acc[mi][nt][1]);
                QK[(size_t)(gr0 + 8) * 1024 + wi] =
                    pack_bf16x2(acc[mi][nt][2], acc[mi][nt][3]);
            } else {
                int wi = (gc - 2 * HID) >> 1;
                VH[(size_t)gr0 * 512 + wi] =
                    pack_f16x2(acc[mi][nt][0], acc[mi][nt][1]);
                VH[(size_t)(gr0 + 8) * 512 + wi] =
                    pack_f16x2(acc[mi][nt][2], acc[mi][nt][3]);
            }
        }
    }
}

// ---------------------------------------------------------------------------
// Flash attention + fused out-projection (R16):
//  - R14 compute body: monolithic 8-chain S phase (max tensor ILP),
//    then per-kk ex2 + PV  (the R15 interleave regressed: 4-deep mma chains)
//  - 3-stage cp.async ring, SINGLE __syncthreads per iteration
//  - K B-frags ldmatrix.x4 non-trans; ex2.approx.f16x2; ones-column row-sum
// ---------------------------------------------------------------------------
#define KS2 36
#define VS2 44
#define KBUF (64 * KS2)                 // 2304 words
#define VBUF (64 * VS2)                 // 2816 words
#define VBASE (3 * KBUF)                // 6912
#define WOUT_OFF (3 * KBUF + 3 * VBUF)  // 15360 words
#define FL_SMEM_W (WOUT_OFF + 64 * 36)  // 17664 words
#define FL_SMEM_B (FL_SMEM_W * 4)       // 70656 bytes -> 2 CTAs/SM

__global__ __launch_bounds__(256, 2) void flash_tc_kernel(
    const float* __restrict__ Wout, uint32_t* __restrict__ parth)
{
    extern __shared__ uint32_t sm[];
    uint32_t* Qst = sm + KBUF;          // K buf1+buf2 region (4608 w) as Q staging
    uint32_t* Wsm = sm + WOUT_OFF;      // Wout_h fp16 tile [k=64][32 words], stride 36

    const int tid = threadIdx.x;
    const int w   = tid >> 5;
    const int l   = tid & 31;
    const int lr  = l >> 2;
    const int lc  = l & 3;
    const int bh  = blockIdx.y;
    const int b   = bh >> 4;
    const int h   = bh & 15;
    const int q0  = blockIdx.x * 128;
    const int rowbase = b * SEQ;
    const int m0  = w * 16;

    const uint32_t* qw = g_qk + (size_t)rowbase * 1024 + h * 32;
    const uint32_t* kw = g_qk + (size_t)rowbase * 1024 + 512 + h * 32;
    const uint32_t* vw = g_vh + (size_t)rowbase * 512 + h * 32;

    const uint32_t sb = (uint32_t)__cvta_generic_to_shared(sm);

    // ---- stage Q via scratch (K buf1+2 region), lift to fragments
    for (int i = tid; i < 128 * 8; i += 256) {
        int r  = i >> 3;
        int c4 = (i & 7) << 2;
        *(uint4*)&Qst[r * 36 + c4] = *(const uint4*)&qw[(size_t)(q0 + r) * 1024 + c4];
    }
    // ---- stage Wout_h (64x64 fp32 -> fp16, V-tile layout, stride 36)
    for (int i = tid; i < 64 * 32; i += 256) {
        int r  = i >> 5;
        int cp = i & 31;
        float w0 = Wout[(size_t)(h * 64 + r) * HD + 2 * cp];
        float w1 = Wout[(size_t)(h * 64 + r) * HD + 2 * cp + 1];
        Wsm[r * 36 + cp] = pack_f16x2(w0, w1);
    }
    __syncthreads();

    uint32_t qa[4][4];
    #pragma unroll
    for (int kk = 0; kk < 4; ++kk) {
        int c = kk * 8 + lc;
        qa[kk][0] = Qst[(m0 + lr) * 36 + c];
        qa[kk][1] = Qst[(m0 + lr + 8) * 36 + c];
        qa[kk][2] = Qst[(m0 + lr) * 36 + c + 4];
        qa[kk][3] = Qst[(m0 + lr + 8) * 36 + c + 4];
    }
    __syncthreads();   // Q scratch free before K prefetches reuse it

    // ---- ones/zero columns of all 3 V buffers (words 32..35 per row)
    for (int i = tid; i < 192; i += 256) {
        int r  = i & 63;
        int bi = i >> 6;
        *(uint4*)&sm[VBASE + bi * VBUF + r * VS2 + 32] =
            make_uint4(pack_f16x2(1.0f, 0.0f), 0u, 0u, 0u);
    }

    auto pf = [&](int t) {
        int bi = t % 3;
        int j  = t * 64;
        for (int i = tid; i < 512; i += 256) {
            int r  = i >> 3;
            int c4 = (i & 7) << 2;
            cp_async16(sb + (bi * KBUF + r * KS2 + c4) * 4,
                       &kw[(size_t)(j + r) * 1024 + c4]);
            cp_async16(sb + (VBASE + bi * VBUF + r * VS2 + c4) * 4,
                       &vw[(size_t)(j + r) * 512 + c4]);
        }
        cp_commit();
    };

    pf(0);
    pf(1);

    float oacc[9][4];   // 8 data tiles + 1 ones-column tile (l)
    #pragma unroll
    for (int nt = 0; nt < 9; ++nt)
        oacc[nt][0] = oacc[nt][1] = oacc[nt][2] = oacc[nt][3] = 0.0f;

    const int NT = SEQ / 64;
    for (int t = 0; t < NT; ++t) {
        if (t + 1 < NT) {
            asm volatile("cp.async.wait_group 1;\n");
        } else {
            asm volatile("cp.async.wait_group 0;\n");
        }
        __syncthreads();   // single barrier/iter (ring reuse distance 3, skew <= 1)
        if (t + 2 < NT) pf(t + 2);

        const uint32_t kbase = sb + ((t % 3) * KBUF) * 4;
        const uint32_t vbase = sb + (VBASE + (t % 3) * VBUF) * 4;

        // ---- S' = Q @ K^T (bf16): monolithic phase, 8 independent chains
        float sa[8][4];
        #pragma unroll
        for (int nt = 0; nt < 8; ++nt) {
            sa[nt][0] = sa[nt][1] = sa[nt][2] = sa[nt][3] = 0.0f;
            uint32_t kaddr = kbase + ((nt * 8 + (l & 7)) * KS2 + (l >> 3) * 4) * 4;
            uint32_t kb[8];
            ldmatrix_x4(kb[0], kb[1], kb[2], kb[3], kaddr);
            ldmatrix_x4(kb[4], kb[5], kb[6], kb[7], kaddr + 64);
            #pragma unroll
            for (int kk = 0; kk < 4; ++kk)
                mma_bf16(sa[nt], qa[kk][0], qa[kk][1], qa[kk][2], qa[kk][3],
                         kb[2 * kk], kb[2 * kk + 1]);
        }

        // ---- P = 2^(S') fp16x2 + O += P@V (per kk chunk, as R14)
        #pragma unroll
        for (int kk = 0; kk < 4; ++kk) {
            uint32_t pa0 = ex2_h2(pack_f16x2(sa[2 * kk][0],     sa[2 * kk][1]));
            uint32_t pa1 = ex2_h2(pack_f16x2(sa[2 * kk][2],     sa[2 * kk][3]));
            uint32_t pa2 = ex2_h2(pack_f16x2(sa[2 * kk + 1][0], sa[2 * kk + 1][1]));
            uint32_t pa3 = ex2_h2(pack_f16x2(sa[2 * kk + 1][2], sa[2 * kk + 1][3]));
            uint32_t vrow = vbase + (((kk * 16 + (l & 15)) * VS2 + (l >> 4) * 4) * 4);
            #pragma unroll
            for (int g = 0; g < 4; ++g) {
                uint32_t b0, b1, b2, b3;
                ldmatrix_x4_trans(b0, b1, b2, b3, vrow + g * 8 * 4);
                mma_f16(oacc[2 * g],     pa0, pa1, pa2, pa3, b0, b1);
                mma_f16(oacc[2 * g + 1], pa0, pa1, pa2, pa3, b2, b3);
            }
            // ones-column tile: accumulates row sum l into oacc[8]
            uint32_t ob0, ob1;
            ldmatrix_x2_trans(ob0, ob1,
                vbase + (((kk * 16 + (l & 15)) * VS2 + 32) * 4));
            mma_f16(oacc[8], pa0, pa1, pa2, pa3, ob0, ob1);
        }
    }

    // ---- l lives in oacc[8][0] (row lr) / oacc[8][2] (row lr+8) of lc==0 lanes
    float l0 = __shfl_sync(0xffffffffu, oacc[8][0], l & ~3);
    float l1 = __shfl_sync(0xffffffffu, oacc[8][2], l & ~3);
    float inv0 = 1.0f / l0;
    float inv1 = 1.0f / l1;

    // ---- FUSED epilogue: partial_h = O_norm @ Wout_h (fp16 mma)
    float pacc[8][4];
    #pragma unroll
    for (int nt = 0; nt < 8; ++nt)
        pacc[nt][0] = pacc[nt][1] = pacc[nt][2] = pacc[nt][3] = 0.0f;

    const uint32_t wbase = sb + WOUT_OFF * 4;
    #pragma unroll
    for (int kk = 0; kk < 4; ++kk) {
        uint32_t a0 = pack_f16x2(oacc[2 * kk][0] * inv0,     oacc[2 * kk][1] * inv0);
        uint32_t a1 = pack_f16x2(oacc[2 * kk][2] * inv1,     oacc[2 * kk][3] * inv1);
        uint32_t a2 = pack_f16x2(oacc[2 * kk + 1][0] * inv0, oacc[2 * kk + 1][1] * inv0);
        uint32_t a3 = pack_f16x2(oacc[2 * kk + 1][2] * inv1, oacc[2 * kk + 1][3] * inv1);
        uint32_t wrow = wbase + (((kk * 16 + (l & 15)) * 36 + (l >> 4) * 4) * 4);
        #pragma unroll
        for (int g = 0; g < 4; ++g) {
            uint32_t b0, b1, b2, b3;
            ldmatrix_x4_trans(b0, b1, b2, b3, wrow + g * 8 * 4);
            mma_f16(pacc[2 * g],     a0, a1, a2, a3, b0, b1);
            mma_f16(pacc[2 * g + 1], a0, a1, a2, a3, b2, b3);
        }
    }

    // write fp16x2 partials: [h][row][32 words]
    uint32_t* Pp = parth + (size_t)h * ROWS * 32;
    size_t pr0 = (size_t)(rowbase + q0 + m0 + lr) * 32;
    size_t pr1 = pr0 + 8 * 32;
    #pragma unroll
    for (int nt = 0; nt < 8; ++nt) {
        int wi = nt * 4 + lc;
        Pp[pr0 + wi] = pack_f16x2(pacc[nt][0], pacc[nt][1]);
        Pp[pr1 + wi] = pack_f16x2(pacc[nt][2], pacc[nt][3]);
    }
}

// ---------------------------------------------------------------------------
// Final reduce: out = sum_h part[h] (uint4/thread, 16-deep MLP, fp32 acc)
// ---------------------------------------------------------------------------
__global__ __launch_bounds__(256) void head_reduce_kernel(
    const uint32_t* __restrict__ P, float* __restrict__ out)
{
    int wi = (blockIdx.x * 256 + threadIdx.x) * 4;   // 4 words = 8 halves
    const size_t stride = (size_t)ROWS * 32;
    float4 s0 = make_float4(0.f, 0.f, 0.f, 0.f);
    float4 s1 = make_float4(0.f, 0.f, 0.f, 0.f);
    #pragma unroll
    for (int k = 0; k < NHEADS; ++k) {
        uint4 p = *(const uint4*)&P[k * stride + wi];
        float2 a = __half22float2(*(__half2*)&p.x);
        float2 b = __half22float2(*(__half2*)&p.y);
        float2 c = __half22float2(*(__half2*)&p.z);
        float2 d = __half22float2(*(__half2*)&p.w);
        s0.x += a.x; s0.y += a.y; s0.z += b.x; s0.w += b.y;
        s1.x += c.x; s1.y += c.y; s1.z += d.x; s1.w += d.y;
    }
    *(float4*)&out[wi * 2]     = s0;
    *(float4*)&out[wi * 2 + 4] = s1;
}

// ---------------------------------------------------------------------------
extern "C" void kernel_launch(void* const* d_in, const int* in_sizes, int n_in,
                              void* d_out, int out_size)
{
    const float* array = (const float*)d_in[0];   // (2,2048,256)
    const float* Wqkv  = (const float*)d_in[1];   // (256,3072)
    const float* Wout  = (const float*)d_in[2];   // (1024,64)
    float* out = (float*)d_out;                   // (2,2048,64)

    __half *ah, *wh;
    uint32_t *qk, *vh, *parth;
    cudaGetSymbolAddress((void**)&ah,    g_ah);
    cudaGetSymbolAddress((void**)&wh,    g_wh);
    cudaGetSymbolAddress((void**)&qk,    g_qk);
    cudaGetSymbolAddress((void**)&vh,    g_vh);
    cudaGetSymbolAddress((void**)&parth, g_parth);

    cudaFuncSetAttribute(gemm_qkv_f16,
                         cudaFuncAttributeMaxDynamicSharedMemorySize, G1_SMEM_B);
    cudaFuncSetAttribute(flash_tc_kernel,
                         cudaFuncAttributeMaxDynamicSharedMemorySize, FL_SMEM_B);

    // 0) pre-convert inputs to fp16
    f32to16_kernel<<<ROWS * CDIM / 4 / 256, 256>>>(array, (uint32_t*)ah);
    f32to16_kernel<<<CDIM * QKVW / 4 / 256, 256>>>(Wqkv, (uint32_t*)wh);

    // 1) qkv projection (pure fp16 mma, cp.async pipelined)
    gemm_qkv_f16<<<dim3(QKVW / 128, ROWS / 128), 256, G1_SMEM_B>>>(ah, wh, qk, vh);

    // 2) flash attention + fused out-projection (R14 body + 3-stage ring)
    flash_tc_kernel<<<dim3(SEQ / 128, BSZ * NHEADS), 256, FL_SMEM_B>>>(Wout, parth);

    // 3) deterministic reduce over heads
    head_reduce_kernel<<<ROWS * 32 / 4 / 256, 256>>>(parth, out);
}

// round 17
// speedup vs baseline: 1.0727x; 1.0727x over previous
#include <cuda_runtime.h>
#include <cuda_bf16.h>
#include <cuda_fp16.h>
#include <math.h>
#include <stdint.h>

#define NHEADS 16
#define BSZ    2
#define SEQ    2048
#define CDIM   256
#define HID    1024
#define HD     64
#define ROWS   (BSZ * SEQ)   // 4096
#define QKVW   (3 * HID)     // 3072

// Scratch (allocation-free rule: __device__ globals)
__device__ __half   g_ah[(size_t)ROWS * CDIM];        // 2 MB: array fp16
__device__ __half   g_wh[(size_t)CDIM * QKVW];        // 1.5 MB: Wqkv fp16
__device__ uint32_t g_qk[(size_t)ROWS * 1024];        // 16 MB: q|k bf16x2
__device__ uint32_t g_vh[(size_t)ROWS * 512];         //  8 MB: v fp16x2
__device__ uint32_t g_parth[(size_t)NHEADS * ROWS * 32]; // 8 MB: per-head partials fp16x2

// ---------------------------------------------------------------------------
// helpers
// ---------------------------------------------------------------------------
__device__ __forceinline__ uint32_t pack_bf16x2(float lo, float hi) {
    __nv_bfloat162 h = __floats2bfloat162_rn(lo, hi);
    return *(uint32_t*)&h;
}

__device__ __forceinline__ uint32_t pack_f16x2(float lo, float hi) {
    __half2 h = __floats2half2_rn(lo, hi);
    return *(uint32_t*)&h;
}

__device__ __forceinline__ uint32_t ex2_h2(uint32_t x) {
    uint32_t r;
    asm("ex2.approx.f16x2 %0, %1;\n" : "=r"(r) : "r"(x));
    return r;
}

__device__ __forceinline__ void mma_bf16(
    float* d, uint32_t a0, uint32_t a1, uint32_t a2, uint32_t a3,
    uint32_t b0, uint32_t b1)
{
    asm volatile(
        "mma.sync.aligned.m16n8k16.row.col.f32.bf16.bf16.f32 "
        "{%0,%1,%2,%3}, {%4,%5,%6,%7}, {%8,%9}, {%0,%1,%2,%3};\n"
        : "+f"(d[0]), "+f"(d[1]), "+f"(d[2]), "+f"(d[3])
        : "r"(a0), "r"(a1), "r"(a2), "r"(a3), "r"(b0), "r"(b1));
}

__device__ __forceinline__ void mma_f16(
    float* d, uint32_t a0, uint32_t a1, uint32_t a2, uint32_t a3,
    uint32_t b0, uint32_t b1)
{
    asm volatile(
        "mma.sync.aligned.m16n8k16.row.col.f32.f16.f16.f32 "
        "{%0,%1,%2,%3}, {%4,%5,%6,%7}, {%8,%9}, {%0,%1,%2,%3};\n"
        : "+f"(d[0]), "+f"(d[1]), "+f"(d[2]), "+f"(d[3])
        : "r"(a0), "r"(a1), "r"(a2), "r"(a3), "r"(b0), "r"(b1));
}

__device__ __forceinline__ void ldmatrix_x4(
    uint32_t& r0, uint32_t& r1, uint32_t& r2, uint32_t& r3, uint32_t addr)
{
    asm volatile(
        "ldmatrix.sync.aligned.m8n8.x4.shared.b16 {%0,%1,%2,%3}, [%4];\n"
        : "=r"(r0), "=r"(r1), "=r"(r2), "=r"(r3) : "r"(addr));
}

__device__ __forceinline__ void ldmatrix_x4_trans(
    uint32_t& r0, uint32_t& r1, uint32_t& r2, uint32_t& r3, uint32_t addr)
{
    asm volatile(
        "ldmatrix.sync.aligned.m8n8.x4.trans.shared.b16 {%0,%1,%2,%3}, [%4];\n"
        : "=r"(r0), "=r"(r1), "=r"(r2), "=r"(r3) : "r"(addr));
}

__device__ __forceinline__ void ldmatrix_x2_trans(
    uint32_t& r0, uint32_t& r1, uint32_t addr)
{
    asm volatile(
        "ldmatrix.sync.aligned.m8n8.x2.trans.shared.b16 {%0,%1}, [%2];\n"
        : "=r"(r0), "=r"(r1) : "r"(addr));
}

__device__ __forceinline__ void cp_async16(uint32_t smem_addr, const void* gptr) {
    asm volatile("cp.async.cg.shared.global [%0], [%1], 16;\n"
                 :: "r"(smem_addr), "l"(gptr));
}
__device__ __forceinline__ void cp_commit() {
    asm volatile("cp.async.commit_group;\n");
}

// ---------------------------------------------------------------------------
// fp32 -> fp16 pre-convert
// ---------------------------------------------------------------------------
__global__ __launch_bounds__(256) void f32to16_kernel(
    const float* __restrict__ src, uint32_t* __restrict__ dst)
{
    int i = (blockIdx.x * 256 + threadIdx.x) * 4;
    float4 v = *(const float4*)&src[i];
    uint2 o = make_uint2(pack_f16x2(v.x, v.y), pack_f16x2(v.z, v.w));
    *(uint2*)&dst[i >> 1] = o;
}

// ---------------------------------------------------------------------------
// GEMM1: qkv = array @ Wqkv, pure fp16 mma (proven R12). Epilogue:
// q -> bf16 (x 0.125*log2e), k -> bf16, v -> fp16.
// ---------------------------------------------------------------------------
#define QSCALE 0.180336880f   // 0.125 * log2(e)
#define G1AS 40
#define G1BS 136
#define G1A_H (128 * G1AS)
#define G1B_H (32 * G1BS)
#define G1STAGE_H (G1A_H + G1B_H)
#define G1_SMEM_B (2 * G1STAGE_H * 2)   // 37888 bytes

__global__ __launch_bounds__(256, 2) void gemm_qkv_f16(
    const __half* __restrict__ A, const __half* __restrict__ W,
    uint32_t* __restrict__ QK, uint32_t* __restrict__ VH)
{
    extern __shared__ __half hsm[];

    const int tid = threadIdx.x;
    const int w   = tid >> 5;
    const int wr  = w >> 2;
    const int wc  = w & 3;
    const int l   = tid & 31;
    const int lr  = l >> 2;
    const int lc  = l & 3;
    const int row0 = blockIdx.y * 128;
    const int col0 = blockIdx.x * 128;

    const uint32_t sb = (uint32_t)__cvta_generic_to_shared(hsm);

    auto prefetch = [&](int kt, int s) {
        const int k0 = kt * 32;
        const uint32_t abase = sb + (s * G1STAGE_H) * 2;
        const uint32_t bbase = abase + G1A_H * 2;
        #pragma unroll
        for (int i = 0; i < 2; ++i) {
            int idx = i * 256 + tid;
            int r   = idx >> 2;
            int c8  = (idx & 3) << 3;
            cp_async16(abase + (r * G1AS + c8) * 2,
                       &A[(size_t)(row0 + r) * CDIM + k0 + c8]);
        }
        #pragma unroll
        for (int i = 0; i < 2; ++i) {
            int idx = i * 256 + tid;
            int r   = idx >> 4;
            int c8  = (idx & 15) << 3;
            cp_async16(bbase + (r * G1BS + c8) * 2,
                       &W[(size_t)(k0 + r) * QKVW + col0 + c8]);
        }
        cp_commit();
    };

    float acc[4][4][4] = {};

    prefetch(0, 0);

    const int NKT = CDIM / 32;   // 8
    for (int kt = 0; kt < NKT; ++kt) {
        if (kt + 1 < NKT) {
            prefetch(kt + 1, (kt + 1) & 1);
            asm volatile("cp.async.wait_group 1;\n");
        } else {
            asm volatile("cp.async.wait_group 0;\n");
        }
        __syncthreads();

        const uint32_t sa = sb + ((kt & 1) * G1STAGE_H) * 2;
        const uint32_t sB = sa + G1A_H * 2;

        #pragma unroll
        for (int ks = 0; ks < 2; ++ks) {
            uint32_t af[4][4];
            #pragma unroll
            for (int mi = 0; mi < 4; ++mi) {
                uint32_t addr = sa +
                    ((wr * 64 + mi * 16 + (l & 15)) * G1AS + ks * 16 + (l >> 4) * 8) * 2;
                ldmatrix_x4(af[mi][0], af[mi][1], af[mi][2], af[mi][3], addr);
            }
            uint32_t bf[2][4];
            #pragma unroll
            for (int g = 0; g < 2; ++g) {
                uint32_t addr = sB +
                    ((ks * 16 + (l & 15)) * G1BS + wc * 32 + g * 16 + (l >> 4) * 8) * 2;
                ldmatrix_x4_trans(bf[g][0], bf[g][1], bf[g][2], bf[g][3], addr);
            }
            #pragma unroll
            for (int mi = 0; mi < 4; ++mi)
                #pragma unroll
                for (int g = 0; g < 2; ++g) {
                    mma_f16(acc[mi][2 * g],     af[mi][0], af[mi][1], af[mi][2], af[mi][3],
                            bf[g][0], bf[g][1]);
                    mma_f16(acc[mi][2 * g + 1], af[mi][0], af[mi][1], af[mi][2], af[mi][3],
                            bf[g][2], bf[g][3]);
                }
        }
        __syncthreads();
    }

    #pragma unroll
    for (int mi = 0; mi < 4; ++mi) {
        int gr0 = row0 + wr * 64 + mi * 16 + lr;
        #pragma unroll
        for (int nt = 0; nt < 4; ++nt) {
            int gc = col0 + wc * 32 + nt * 8 + 2 * lc;
            if (gc < HID) {
                QK[(size_t)gr0 * 1024 + (gc >> 1)] =
                    pack_bf16x2(acc[mi][nt][0] * QSCALE, acc[mi][nt][1] * QSCALE);
                QK[(size_t)(gr0 + 8) * 1024 + (gc >> 1)] =
                    pack_bf16x2(acc[mi][nt][2] * QSCALE, acc[mi][nt][3] * QSCALE);
            } else if (gc < 2 * HID) {
                int wi = 512 + ((gc - HID) >> 1);
                QK[(size_t)gr0 * 1024 + wi] =
                    pack_bf16x2(acc[mi][nt][0], acc[mi][nt][1]);
                QK[(size_t)(gr0 + 8) * 1024 + wi] =
                    pack_bf16x2(acc[mi][nt][2], acc[mi][nt][3]);
            } else {
                int wi = (gc - 2 * HID) >> 1;
                VH[(size_t)gr0 * 512 + wi] =
                    pack_f16x2(acc[mi][nt][0], acc[mi][nt][1]);
                VH[(size_t)(gr0 + 8) * 512 + wi] =
                    pack_f16x2(acc[mi][nt][2], acc[mi][nt][3]);
            }
        }
    }
}

// ---------------------------------------------------------------------------
// Flash attention + fused out-projection — EXACT R14 structure (proven 112us):
//  - 2-stage cp.async double buffer, pf-before-wait, two __syncthreads/iter
//  - monolithic 8-chain S phase; per-kk ex2 + PV
//  - K B-frags ldmatrix.x4 non-trans; ex2.approx.f16x2; ones-column row-sum
// ---------------------------------------------------------------------------
#define KS2 36
#define VS2 44
#define KBUF (64 * KS2)        // 2304 words
#define VBUF (64 * VS2)        // 2816 words
#define WOUT_OFF (2 * KBUF + 2 * VBUF)   // 10240 words
#define FL_SMEM_W (WOUT_OFF + 64 * 36)   // 12544 words
#define FL_SMEM_B (FL_SMEM_W * 4)        // 50176 bytes -> 2 CTAs/SM

__global__ __launch_bounds__(256, 2) void flash_tc_kernel(
    const float* __restrict__ Wout, uint32_t* __restrict__ parth)
{
    extern __shared__ uint32_t sm[];
    uint32_t* Qst = sm + KBUF;          // K buf1 + V buf0 region as Q staging scratch
    uint32_t* Wsm = sm + WOUT_OFF;      // Wout_h fp16 tile [k=64][32 words], stride 36

    const int tid = threadIdx.x;
    const int w   = tid >> 5;
    const int l   = tid & 31;
    const int lr  = l >> 2;
    const int lc  = l & 3;
    const int bh  = blockIdx.y;
    const int b   = bh >> 4;
    const int h   = bh & 15;
    const int q0  = blockIdx.x * 128;
    const int rowbase = b * SEQ;
    const int m0  = w * 16;

    const uint32_t* qw = g_qk + (size_t)rowbase * 1024 + h * 32;
    const uint32_t* kw = g_qk + (size_t)rowbase * 1024 + 512 + h * 32;
    const uint32_t* vw = g_vh + (size_t)rowbase * 512 + h * 32;

    const uint32_t sb = (uint32_t)__cvta_generic_to_shared(sm);

    // ---- stage Q via scratch, lift to fragments
    for (int i = tid; i < 128 * 8; i += 256) {
        int r  = i >> 3;
        int c4 = (i & 7) << 2;
        *(uint4*)&Qst[r * 36 + c4] = *(const uint4*)&qw[(size_t)(q0 + r) * 1024 + c4];
    }
    // ---- stage Wout_h (64x64 fp32 -> fp16, V-tile layout, stride 36)
    for (int i = tid; i < 64 * 32; i += 256) {
        int r  = i >> 5;
        int cp = i & 31;
        float w0 = Wout[(size_t)(h * 64 + r) * HD + 2 * cp];
        float w1 = Wout[(size_t)(h * 64 + r) * HD + 2 * cp + 1];
        Wsm[r * 36 + cp] = pack_f16x2(w0, w1);
    }
    __syncthreads();

    uint32_t qa[4][4];
    #pragma unroll
    for (int kk = 0; kk < 4; ++kk) {
        int c = kk * 8 + lc;
        qa[kk][0] = Qst[(m0 + lr) * 36 + c];
        qa[kk][1] = Qst[(m0 + lr + 8) * 36 + c];
        qa[kk][2] = Qst[(m0 + lr) * 36 + c + 4];
        qa[kk][3] = Qst[(m0 + lr + 8) * 36 + c + 4];
    }
    __syncthreads();   // Q scratch free (overlaps K buf1 + V buf0)

    // ---- init ones/zero columns of both V buffers (words 32..35 of each row)
    for (int i = tid; i < 128; i += 256) {
        int r  = i & 63;
        int bi = i >> 6;
        *(uint4*)&sm[2 * KBUF + bi * VBUF + r * VS2 + 32] =
            make_uint4(pack_f16x2(1.0f, 0.0f), 0u, 0u, 0u);
    }

    // ---- prefetch K/V tile 0 into buffer 0
    for (int i = tid; i < 512; i += 256) {
        int r  = i >> 3;
        int c4 = (i & 7) << 2;
        cp_async16(sb + (r * KS2 + c4) * 4,              &kw[(size_t)r * 1024 + c4]);
        cp_async16(sb + (2 * KBUF + r * VS2 + c4) * 4,   &vw[(size_t)r * 512 + c4]);
    }
    cp_commit();

    float oacc[9][4];   // 8 data tiles + 1 tile holding the ones-column (l)
    #pragma unroll
    for (int nt = 0; nt < 9; ++nt)
        oacc[nt][0] = oacc[nt][1] = oacc[nt][2] = oacc[nt][3] = 0.0f;

    const int NT = SEQ / 64;
    for (int t = 0; t < NT; ++t) {
        if (t + 1 < NT) {
            const int j1 = (t + 1) * 64;
            const int bi = (t + 1) & 1;
            for (int i = tid; i < 512; i += 256) {
                int r  = i >> 3;
                int c4 = (i & 7) << 2;
                cp_async16(sb + (bi * KBUF + r * KS2 + c4) * 4,
                           &kw[(size_t)(j1 + r) * 1024 + c4]);
                cp_async16(sb + (2 * KBUF + bi * VBUF + r * VS2 + c4) * 4,
                           &vw[(size_t)(j1 + r) * 512 + c4]);
            }
            cp_commit();
            asm volatile("cp.async.wait_group 1;\n");
        } else {
            asm volatile("cp.async.wait_group 0;\n");
        }
        __syncthreads();

        const uint32_t kbase = sb + ((t & 1) * KBUF) * 4;
        const uint32_t vbase = sb + (2 * KBUF + (t & 1) * VBUF) * 4;

        // ---- S' = Q @ K^T (bf16): K B-frags via ldmatrix.x4 non-trans
        float sa[8][4];
        #pragma unroll
        for (int nt = 0; nt < 8; ++nt) {
            sa[nt][0] = sa[nt][1] = sa[nt][2] = sa[nt][3] = 0.0f;
            uint32_t kaddr = kbase + ((nt * 8 + (l & 7)) * KS2 + (l >> 3) * 4) * 4;
            uint32_t kb[8];
            ldmatrix_x4(kb[0], kb[1], kb[2], kb[3], kaddr);
            ldmatrix_x4(kb[4], kb[5], kb[6], kb[7], kaddr + 64);
            #pragma unroll
            for (int kk = 0; kk < 4; ++kk)
                mma_bf16(sa[nt], qa[kk][0], qa[kk][1], qa[kk][2], qa[kk][3],
                         kb[2 * kk], kb[2 * kk + 1]);
        }

        // ---- P = 2^(S') in fp16x2 (one MUFU per pair) + O += P@V
        #pragma unroll
        for (int kk = 0; kk < 4; ++kk) {
            uint32_t pa0 = ex2_h2(pack_f16x2(sa[2 * kk][0],     sa[2 * kk][1]));
            uint32_t pa1 = ex2_h2(pack_f16x2(sa[2 * kk][2],     sa[2 * kk][3]));
            uint32_t pa2 = ex2_h2(pack_f16x2(sa[2 * kk + 1][0], sa[2 * kk + 1][1]));
            uint32_t pa3 = ex2_h2(pack_f16x2(sa[2 * kk + 1][2], sa[2 * kk + 1][3]));
            uint32_t vrow = vbase + (((kk * 16 + (l & 15)) * VS2 + (l >> 4) * 4) * 4);
            #pragma unroll
            for (int g = 0; g < 4; ++g) {
                uint32_t b0, b1, b2, b3;
                ldmatrix_x4_trans(b0, b1, b2, b3, vrow + g * 8 * 4);
                mma_f16(oacc[2 * g],     pa0, pa1, pa2, pa3, b0, b1);
                mma_f16(oacc[2 * g + 1], pa0, pa1, pa2, pa3, b2, b3);
            }
            // ones-column tile (cols 64-71): accumulates row sum l into oacc[8]
            uint32_t ob0, ob1;
            ldmatrix_x2_trans(ob0, ob1,
                vbase + (((kk * 16 + (l & 15)) * VS2 + 32) * 4));
            mma_f16(oacc[8], pa0, pa1, pa2, pa3, ob0, ob1);
        }
        __syncthreads();   // done with this K/V buffer before next prefetch lands
    }

    // ---- l lives in oacc[8][0] (row lr) / oacc[8][2] (row lr+8) of lc==0 lanes
    float l0 = __shfl_sync(0xffffffffu, oacc[8][0], l & ~3);
    float l1 = __shfl_sync(0xffffffffu, oacc[8][2], l & ~3);
    float inv0 = 1.0f / l0;
    float inv1 = 1.0f / l1;

    // ---- FUSED epilogue: partial_h = O_norm @ Wout_h (fp16 mma)
    float pacc[8][4];
    #pragma unroll
    for (int nt = 0; nt < 8; ++nt)
        pacc[nt][0] = pacc[nt][1] = pacc[nt][2] = pacc[nt][3] = 0.0f;

    const uint32_t wbase = sb + WOUT_OFF * 4;
    #pragma unroll
    for (int kk = 0; kk < 4; ++kk) {
        uint32_t a0 = pack_f16x2(oacc[2 * kk][0] * inv0,     oacc[2 * kk][1] * inv0);
        uint32_t a1 = pack_f16x2(oacc[2 * kk][2] * inv1,     oacc[2 * kk][3] * inv1);
        uint32_t a2 = pack_f16x2(oacc[2 * kk + 1][0] * inv0, oacc[2 * kk + 1][1] * inv0);
        uint32_t a3 = pack_f16x2(oacc[2 * kk + 1][2] * inv1, oacc[2 * kk + 1][3] * inv1);
        uint32_t wrow = wbase + (((kk * 16 + (l & 15)) * 36 + (l >> 4) * 4) * 4);
        #pragma unroll
        for (int g = 0; g < 4; ++g) {
            uint32_t b0, b1, b2, b3;
            ldmatrix_x4_trans(b0, b1, b2, b3, wrow + g * 8 * 4);
            mma_f16(pacc[2 * g],     a0, a1, a2, a3, b0, b1);
            mma_f16(pacc[2 * g + 1], a0, a1, a2, a3, b2, b3);
        }
    }

    // write fp16x2 partials: [h][row][32 words]
    uint32_t* Pp = parth + (size_t)h * ROWS * 32;
    size_t pr0 = (size_t)(rowbase + q0 + m0 + lr) * 32;
    size_t pr1 = pr0 + 8 * 32;
    #pragma unroll
    for (int nt = 0; nt < 8; ++nt) {
        int wi = nt * 4 + lc;
        Pp[pr0 + wi] = pack_f16x2(pacc[nt][0], pacc[nt][1]);
        Pp[pr1 + wi] = pack_f16x2(pacc[nt][2], pacc[nt][3]);
    }
}

// ---------------------------------------------------------------------------
// Final reduce: out = sum_h part[h] (uint4/thread, 16-deep MLP, fp32 acc)
// ---------------------------------------------------------------------------
__global__ __launch_bounds__(256) void head_reduce_kernel(
    const uint32_t* __restrict__ P, float* __restrict__ out)
{
    int wi = (blockIdx.x * 256 + threadIdx.x) * 4;   // 4 words = 8 halves
    const size_t stride = (size_t)ROWS * 32;
    float4 s0 = make_float4(0.f, 0.f, 0.f, 0.f);
    float4 s1 = make_float4(0.f, 0.f, 0.f, 0.f);
    #pragma unroll
    for (int k = 0; k < NHEADS; ++k) {
        uint4 p = *(const uint4*)&P[k * stride + wi];
        float2 a = __half22float2(*(__half2*)&p.x);
        float2 b = __half22float2(*(__half2*)&p.y);
        float2 c = __half22float2(*(__half2*)&p.z);
        float2 d = __half22float2(*(__half2*)&p.w);
        s0.x += a.x; s0.y += a.y; s0.z += b.x; s0.w += b.y;
        s1.x += c.x; s1.y += c.y; s1.z += d.x; s1.w += d.y;
    }
    *(float4*)&out[wi * 2]     = s0;
    *(float4*)&out[wi * 2 + 4] = s1;
}

// ---------------------------------------------------------------------------
extern "C" void kernel_launch(void* const* d_in, const int* in_sizes, int n_in,
                              void* d_out, int out_size)
{
    const float* array = (const float*)d_in[0];   // (2,2048,256)
    const float* Wqkv  = (const float*)d_in[1];   // (256,3072)
    const float* Wout  = (const float*)d_in[2];   // (1024,64)
    float* out = (float*)d_out;                   // (2,2048,64)

    __half *ah, *wh;
    uint32_t *qk, *vh, *parth;
    cudaGetSymbolAddress((void**)&ah,    g_ah);
    cudaGetSymbolAddress((void**)&wh,    g_wh);
    cudaGetSymbolAddress((void**)&qk,    g_qk);
    cudaGetSymbolAddress((void**)&vh,    g_vh);
    cudaGetSymbolAddress((void**)&parth, g_parth);

    cudaFuncSetAttribute(gemm_qkv_f16,
                         cudaFuncAttributeMaxDynamicSharedMemorySize, G1_SMEM_B);
    cudaFuncSetAttribute(flash_tc_kernel,
                         cudaFuncAttributeMaxDynamicSharedMemorySize, FL_SMEM_B);

    // 0) pre-convert inputs to fp16
    f32to16_kernel<<<ROWS * CDIM / 4 / 256, 256>>>(array, (uint32_t*)ah);
    f32to16_kernel<<<CDIM * QKVW / 4 / 256, 256>>>(Wqkv, (uint32_t*)wh);

    // 1) qkv projection (pure fp16 mma, cp.async pipelined)
    gemm_qkv_f16<<<dim3(QKVW / 128, ROWS / 128), 256, G1_SMEM_B>>>(ah, wh, qk, vh);

    // 2) flash attention + fused out-projection (exact R14 structure)
    flash_tc_kernel<<<dim3(SEQ / 128, BSZ * NHEADS), 256, FL_SMEM_B>>>(Wout, parth);

    // 3) deterministic reduce over heads
    head_reduce_kernel<<<ROWS * 32 / 4 / 256, 256>>>(parth, out);
}